// round 16
// baseline (speedup 1.0000x reference)
#include <cuda_runtime.h>
#include <cuda_fp16.h>
#include <mma.h>
#include <cstdint>

using namespace nvcuda;

#define N_NODES 100000
#define N_PAD   100096   // 782 * 128
#define N_EDGES 3200000
#define H 128
#define HQ 256
#define A_DIM 10
#define NBLK_SCAN 98
#define XN4 (N_NODES * H / 4)   // 3,200,000 float4 slots for x

static inline int cdiv(int a, int b) { return (a + b - 1) / b; }

// ---------------- scratch ----------------
__device__ __half g_x16[(size_t)N_PAD * H];   // fp16 copy of x
__device__ __half g_xw16[(size_t)N_PAD * H];  // fp16 relu(x@We+be)@Wg (UNscaled)
__device__ __half g_h216[(size_t)N_PAD * H];  // fp16 relu(gcn agg)
__device__ __half g_W116[HQ * H];             // fp16 W1 [128,256]
__device__ __half g_Wg16[H * H];              // fp16 W_gcn
__device__ __half g_We16[H * H];              // fp16 W_enc
__device__ float  g_dinv[N_NODES];
__device__ int    g_deg[N_NODES];
__device__ int    g_rowptr[N_NODES + 1];
__device__ int    g_csrc[N_EDGES];
__device__ unsigned g_dr[N_EDGES];            // packed: dst | (rank << 17)
__device__ int    g_is32;
__device__ unsigned long long g_desc[NBLK_SCAN];   // decoupled-lookback descriptors

// ---------------- cp.async helpers ----------------
__device__ __forceinline__ void cp16(void* s, const void* g, bool p) {
    uint32_t sa = (uint32_t)__cvta_generic_to_shared(s);
    int sz = p ? 16 : 0;
    asm volatile("cp.async.cg.shared.global [%0], [%1], 16, %2;\n"
                 :: "r"(sa), "l"(g), "r"(sz));
}
__device__ __forceinline__ void cp_commit() {
    asm volatile("cp.async.commit_group;\n");
}
template <int NN>
__device__ __forceinline__ void cp_wait() {
    asm volatile("cp.async.wait_group %0;\n" :: "n"(NN));
}

// ---------------- merged fp32 -> fp16 conversion (x + all weights) ----------------
__global__ void k_cvtAll(const float* __restrict__ x,  const float* __restrict__ W1,
                         const float* __restrict__ Wg, const float* __restrict__ We) {
    int i = blockIdx.x * blockDim.x + threadIdx.x;
    const float* src; __half* dst; int off;
    if (i < XN4)               { src = x;  dst = g_x16;  off = i; }
    else if (i < XN4 + 8192)   { src = W1; dst = g_W116; off = i - XN4; }
    else if (i < XN4 + 12288)  { src = Wg; dst = g_Wg16; off = i - XN4 - 8192; }
    else if (i < XN4 + 16384)  { src = We; dst = g_We16; off = i - XN4 - 12288; }
    else return;
    float4 v = *(const float4*)&src[(size_t)off * 4];
    __half2 h0 = __floats2half2_rn(v.x, v.y);
    __half2 h1 = __floats2half2_rn(v.z, v.w);
    uint2 u;
    u.x = *(uint32_t*)&h0;
    u.y = *(uint32_t*)&h1;
    *(uint2*)&dst[(size_t)off * 4] = u;
}

// ---------------- init: dtype detect + zero deg + zero scan descriptors ----------------
__global__ void k_init(const void* ei) {
    int i = blockIdx.x * blockDim.x + threadIdx.x;
    if (i < N_NODES) g_deg[i] = 0;
    if (i < NBLK_SCAN) g_desc[i] = 0ull;
    if (i == 0) {
        const long long* p = (const long long*)ei;
        int is32 = 0;
        for (int k = 0; k < 64; k++) {
            long long v = p[k];
            if (v < 0 || v >= (long long)N_NODES) { is32 = 1; break; }
        }
        g_is32 = is32;
    }
}

// histogram over dst half; 8 edges/thread; store packed dst|rank<<17
__global__ void k_hist(const void* ei) {
    int i = blockIdx.x * blockDim.x + threadIdx.x;
    int base = i * 8;
    if (base >= N_EDGES) return;
    int d[8];
    if (g_is32) {
        int4 p0 = ((const int4*)ei)[N_EDGES / 4 + i * 2];
        int4 p1 = ((const int4*)ei)[N_EDGES / 4 + i * 2 + 1];
        d[0] = p0.x; d[1] = p0.y; d[2] = p0.z; d[3] = p0.w;
        d[4] = p1.x; d[5] = p1.y; d[6] = p1.z; d[7] = p1.w;
    } else {
#pragma unroll
        for (int q = 0; q < 4; q++) {
            longlong2 a = ((const longlong2*)ei)[N_EDGES / 2 + i * 4 + q];
            d[q * 2] = (int)a.x; d[q * 2 + 1] = (int)a.y;
        }
    }
    unsigned pk[8];
#pragma unroll
    for (int q = 0; q < 8; q++) {
        unsigned r = (unsigned)atomicAdd(&g_deg[d[q]], 1);
        pk[q] = (unsigned)d[q] | (r << 17);
    }
    *(uint4*)&g_dr[base]     = make_uint4(pk[0], pk[1], pk[2], pk[3]);
    *(uint4*)&g_dr[base + 4] = make_uint4(pk[4], pk[5], pk[6], pk[7]);
}

// ---------- single-kernel scan: decoupled lookback (98 co-resident blocks) ----------
__global__ __launch_bounds__(1024) void k_scan() {
    __shared__ int warpsum[32];
    __shared__ int s_prefix;
    const int b = blockIdx.x;
    int tid = threadIdx.x, lane = tid & 31, wid = tid >> 5;
    int i = b * 1024 + tid;
    int v = (i < N_NODES) ? g_deg[i] : 0;
    int x = v;
#pragma unroll
    for (int off = 1; off < 32; off <<= 1) {
        int y = __shfl_up_sync(0xffffffffu, x, off);
        if (lane >= off) x += y;
    }
    if (lane == 31) warpsum[wid] = x;
    __syncthreads();
    if (wid == 0) {
        int w = warpsum[lane];
#pragma unroll
        for (int off = 1; off < 32; off <<= 1) {
            int y = __shfl_up_sync(0xffffffffu, w, off);
            if (lane >= off) w += y;
        }
        warpsum[lane] = w;
    }
    __syncthreads();
    int incl = x + (wid > 0 ? warpsum[wid - 1] : 0);
    int blocktotal = warpsum[31];

    if (tid == 0) {
        unsigned long long pub =
            ((unsigned long long)(b == 0 ? 2 : 1) << 62) | (unsigned)blocktotal;
        atomicExch(&g_desc[b], pub);
        if (b == 0) s_prefix = 0;
    }

    if (b > 0 && wid == 0) {
        int prefix = 0;
        int j = b - 1;
        while (true) {
            int idx = j - lane;
            int st = 0; unsigned val = 0;
            if (idx >= 0) {
                unsigned long long v64;
                do {
                    v64 = atomicAdd(&g_desc[idx], 0ull);
                    st = (int)(v64 >> 62);
                } while (st == 0);
                val = (unsigned)(v64 & 0xffffffffu);
            }
            unsigned inclmask = __ballot_sync(0xffffffffu, idx >= 0 && st == 2);
            if (inclmask) {
                int closest = __ffs(inclmask) - 1;
                int contrib = (lane <= closest) ? (int)val : 0;
#pragma unroll
                for (int o = 16; o; o >>= 1) contrib += __shfl_xor_sync(0xffffffffu, contrib, o);
                prefix += contrib;
                break;
            } else {
                int contrib = (idx >= 0) ? (int)val : 0;
#pragma unroll
                for (int o = 16; o; o >>= 1) contrib += __shfl_xor_sync(0xffffffffu, contrib, o);
                prefix += contrib;
                j -= 32;
            }
        }
        if (lane == 0) {
            atomicExch(&g_desc[b], (2ull << 62) | (unsigned)(prefix + blocktotal));
            s_prefix = prefix;
        }
    }
    __syncthreads();
    int prefix = s_prefix;

    if (i < N_NODES) {
        g_rowptr[i] = prefix + (incl - v);
        g_dinv[i] = rsqrtf((float)(v + 1));
    }
    if (b == 0 && tid == 0) g_rowptr[N_NODES] = N_EDGES;
}

// fill CSR: atomic-free, 8 edges/thread, pos = rowptr[dst] + rank (packed)
__global__ void k_fill(const void* ei) {
    int i = blockIdx.x * blockDim.x + threadIdx.x;
    int base = i * 8;
    if (base >= N_EDGES) return;
    int s[8];
    if (g_is32) {
        int4 a = ((const int4*)ei)[i * 2];
        int4 b = ((const int4*)ei)[i * 2 + 1];
        s[0] = a.x; s[1] = a.y; s[2] = a.z; s[3] = a.w;
        s[4] = b.x; s[5] = b.y; s[6] = b.z; s[7] = b.w;
    } else {
#pragma unroll
        for (int q = 0; q < 4; q++) {
            longlong2 a = ((const longlong2*)ei)[i * 4 + q];
            s[q * 2] = (int)a.x; s[q * 2 + 1] = (int)a.y;
        }
    }
    uint4 p0 = *(const uint4*)&g_dr[base];
    uint4 p1 = *(const uint4*)&g_dr[base + 4];
    unsigned pk[8] = {p0.x, p0.y, p0.z, p0.w, p1.x, p1.y, p1.z, p1.w};
#pragma unroll
    for (int q = 0; q < 8; q++)
        g_csrc[g_rowptr[pk[q] & 0x1FFFFu] + (pk[q] >> 17)] = s[q];
}

// ========== all-fp16 fused encoder + GCN-weight GEMM, single-shot ==========
#define LDH 136       // halves
#define LDW 132       // floats

__global__ __launch_bounds__(256) void k_enc(const float* __restrict__ b_enc)
{
    extern __shared__ float pool[];
    __half* Hh  = (__half*)pool;                 // 128*136 h
    __half* Wgh = (__half*)(pool + 8704);
    __half* Ah  = (__half*)(pool + 17408);
    __half* Weh = (__half*)(pool + 26112);
    float*  Ts  = pool + 17408;                  // aliases Ah+Weh
    __shared__ float sbe[128];

    const int tid = threadIdx.x;
    const int wid = tid >> 5;
    const int wm = wid & 3, wn = wid >> 2;
    const int rowBase = blockIdx.x * 128;

    if (tid < 128) sbe[tid] = b_enc[tid];

#pragma unroll
    for (int i = 0; i < 8; i++) {
        int slot = tid + i * 256;
        int r = slot >> 4, c8 = (slot & 15) * 8;
        int gr = rowBase + r;
        cp16(&Ah[r * LDH + c8],  &g_x16[(size_t)gr * 128 + c8], gr < N_NODES);
        cp16(&Weh[r * LDH + c8], &g_We16[r * 128 + c8], true);
        cp16(&Wgh[r * LDH + c8], &g_Wg16[r * 128 + c8], true);
    }
    cp_commit();
    cp_wait<0>();
    __syncthreads();

    wmma::fragment<wmma::accumulator, 16, 16, 16, float> acc[2][4];
#pragma unroll
    for (int mt = 0; mt < 2; mt++)
#pragma unroll
        for (int nt = 0; nt < 4; nt++) wmma::fill_fragment(acc[mt][nt], 0.f);

#pragma unroll
    for (int ks = 0; ks < 8; ks++) {
        int k = ks * 16;
        wmma::fragment<wmma::matrix_a, 16, 16, 16, __half, wmma::row_major> af[2];
        wmma::fragment<wmma::matrix_b, 16, 16, 16, __half, wmma::row_major> bf[4];
#pragma unroll
        for (int mt = 0; mt < 2; mt++)
            wmma::load_matrix_sync(af[mt], &Ah[(wm * 32 + mt * 16) * LDH + k], LDH);
#pragma unroll
        for (int nt = 0; nt < 4; nt++)
            wmma::load_matrix_sync(bf[nt], &Weh[k * LDH + wn * 64 + nt * 16], LDH);
#pragma unroll
        for (int mt = 0; mt < 2; mt++)
#pragma unroll
            for (int nt = 0; nt < 4; nt++)
                wmma::mma_sync(acc[mt][nt], af[mt], bf[nt], acc[mt][nt]);
    }
    __syncthreads();

#pragma unroll
    for (int mt = 0; mt < 2; mt++)
#pragma unroll
        for (int nt = 0; nt < 4; nt++)
            wmma::store_matrix_sync(&Ts[(wm * 32 + mt * 16) * LDW + wn * 64 + nt * 16],
                                    acc[mt][nt], LDW, wmma::mem_row_major);
    __syncthreads();

#pragma unroll
    for (int i = 0; i < 16; i++) {
        int slot = tid + i * 256;
        int r = slot >> 5, c4 = (slot & 31) * 4;
        float4 v = *(float4*)&Ts[r * LDW + c4];
        __half2 h0 = __floats2half2_rn(fmaxf(v.x + sbe[c4 + 0], 0.f),
                                       fmaxf(v.y + sbe[c4 + 1], 0.f));
        __half2 h1 = __floats2half2_rn(fmaxf(v.z + sbe[c4 + 2], 0.f),
                                       fmaxf(v.w + sbe[c4 + 3], 0.f));
        uint2 u;
        u.x = *(uint32_t*)&h0;
        u.y = *(uint32_t*)&h1;
        *(uint2*)&Hh[r * LDH + c4] = u;
    }
    __syncthreads();

#pragma unroll
    for (int mt = 0; mt < 2; mt++)
#pragma unroll
        for (int nt = 0; nt < 4; nt++) wmma::fill_fragment(acc[mt][nt], 0.f);

#pragma unroll
    for (int ks = 0; ks < 8; ks++) {
        int k = ks * 16;
        wmma::fragment<wmma::matrix_a, 16, 16, 16, __half, wmma::row_major> af[2];
        wmma::fragment<wmma::matrix_b, 16, 16, 16, __half, wmma::row_major> bf[4];
#pragma unroll
        for (int mt = 0; mt < 2; mt++)
            wmma::load_matrix_sync(af[mt], &Hh[(wm * 32 + mt * 16) * LDH + k], LDH);
#pragma unroll
        for (int nt = 0; nt < 4; nt++)
            wmma::load_matrix_sync(bf[nt], &Wgh[k * LDH + wn * 64 + nt * 16], LDH);
#pragma unroll
        for (int mt = 0; mt < 2; mt++)
#pragma unroll
            for (int nt = 0; nt < 4; nt++)
                wmma::mma_sync(acc[mt][nt], af[mt], bf[nt], acc[mt][nt]);
    }
    __syncthreads();

#pragma unroll
    for (int mt = 0; mt < 2; mt++)
#pragma unroll
        for (int nt = 0; nt < 4; nt++)
            wmma::store_matrix_sync(&Ts[(wm * 32 + mt * 16) * LDW + wn * 64 + nt * 16],
                                    acc[mt][nt], LDW, wmma::mem_row_major);
    __syncthreads();

#pragma unroll
    for (int i = 0; i < 16; i++) {
        int slot = tid + i * 256;
        int r = slot >> 5, c4 = (slot & 31) * 4;
        int gr = rowBase + r;
        float4 v = *(float4*)&Ts[r * LDW + c4];
        __half2 h0 = __floats2half2_rn(v.x, v.y);
        __half2 h1 = __floats2half2_rn(v.z, v.w);
        uint2 u;
        u.x = *(uint32_t*)&h0;
        u.y = *(uint32_t*)&h1;
        *(uint2*)&g_xw16[(size_t)gr * 128 + c4] = u;
    }
}

// ------- GCN aggregation: 2 nodes/warp, 16 lanes x 16B, prefetched indices -------
__device__ __forceinline__ void fma8(float* acc, float c, uint4 u) {
    __half2* h = (__half2*)&u;
#pragma unroll
    for (int q = 0; q < 4; q++) {
        float2 f = __half22float2(h[q]);
        acc[q * 2]     = fmaf(c, f.x, acc[q * 2]);
        acc[q * 2 + 1] = fmaf(c, f.y, acc[q * 2 + 1]);
    }
}

__global__ void k_agg(const float* __restrict__ b_gcn) {
    int warpId = (blockIdx.x * blockDim.x + threadIdx.x) >> 5;
    int lane = threadIdx.x & 31;
    int sub = lane >> 4;
    int l16 = lane & 15;
    unsigned hmask = sub ? 0xFFFF0000u : 0x0000FFFFu;
    int gw = warpId * 2 + sub;
    if (gw >= N_NODES) return;

    int beg = g_rowptr[gw];
    int end = g_rowptr[gw + 1];

    float acc[8];
#pragma unroll
    for (int q = 0; q < 8; q++) acc[q] = 0.f;

    const int colh = l16 * 8;

    // software-pipelined index loads: fetch chunk n+1 while processing chunk n
    int e0 = beg + l16;
    int s = (e0 < end) ? g_csrc[e0] : 0;
    for (int base = beg; base < end; base += 16) {
        int en = base + 16 + l16;
        int snext = (en < end) ? g_csrc[en] : 0;   // prefetch next chunk
        int cnt = min(16, end - base);
        if (cnt == 16) {
#pragma unroll
            for (int j = 0; j < 16; j++) {
                int sj = __shfl_sync(hmask, s, sub * 16 + j);
                float c = g_dinv[sj];
                uint4 u = *(const uint4*)&g_xw16[(size_t)sj * 128 + colh];
                fma8(acc, c, u);
            }
        } else {
            for (int j = 0; j < cnt; j++) {
                int sj = __shfl_sync(hmask, s, sub * 16 + j);
                float c = g_dinv[sj];
                uint4 u = *(const uint4*)&g_xw16[(size_t)sj * 128 + colh];
                fma8(acc, c, u);
            }
        }
        s = snext;
    }

    float di = g_dinv[gw];
    {
        uint4 u = *(const uint4*)&g_xw16[(size_t)gw * 128 + colh];
        fma8(acc, di, u);
    }

    float4 b0 = *(const float4*)&b_gcn[colh];
    float4 b1 = *(const float4*)&b_gcn[colh + 4];
    float bb[8] = {b0.x, b0.y, b0.z, b0.w, b1.x, b1.y, b1.z, b1.w};
    __half2 ho[4];
#pragma unroll
    for (int q = 0; q < 4; q++) {
        float ox = fmaxf(fmaf(di, acc[q * 2],     bb[q * 2]),     0.f);
        float oy = fmaxf(fmaf(di, acc[q * 2 + 1], bb[q * 2 + 1]), 0.f);
        ho[q] = __floats2half2_rn(ox, oy);
    }
    *(uint4*)&g_h216[(size_t)gw * 128 + colh] = *(uint4*)ho;
}

// ========== fused MLP head (fp16 wmma, single K stage) ==========
#define LDA2 136     // halves
#define LDB2 264     // halves
#define LDT 264      // floats

__global__ __launch_bounds__(512) void k_w1out(
    const float* __restrict__ b1, const float* __restrict__ W2,
    const float* __restrict__ b2, float* __restrict__ out)
{
    extern __shared__ float pool[];
    __half* As = (__half*)pool;                 // 128*136 h
    __half* Bs = (__half*)pool + 128 * LDA2;    // 128*264 h
    float*  Ts = pool;                          // alias: 128*264 f
    __shared__ float sW2[HQ * A_DIM];
    __shared__ float sb1[HQ];
    __shared__ float sb2[A_DIM];

    const int tid = threadIdx.x;
    const int wid = tid >> 5, lane = tid & 31;
    const int wm = wid & 3, wn = wid >> 2;
    const int rowBase = blockIdx.x * 128;

    for (int j = tid; j < HQ * A_DIM; j += 512) sW2[j] = W2[j];
    for (int j = tid; j < HQ; j += 512) sb1[j] = b1[j];
    if (tid < A_DIM) sb2[tid] = b2[tid];

#pragma unroll
    for (int i = 0; i < 4; i++) {
        int slot = tid + i * 512;
        int r = slot >> 4, c8 = (slot & 15) * 8;
        cp16(&As[r * LDA2 + c8], &g_h216[(size_t)(rowBase + r) * 128 + c8], true);
    }
#pragma unroll
    for (int i = 0; i < 8; i++) {
        int slot = tid + i * 512;
        int r = slot >> 5, c8 = (slot & 31) * 8;
        cp16(&Bs[r * LDB2 + c8], &g_W116[(size_t)r * 256 + c8], true);
    }
    cp_commit();
    cp_wait<0>();
    __syncthreads();

    wmma::fragment<wmma::accumulator, 16, 16, 16, float> acc[2][4];
#pragma unroll
    for (int mt = 0; mt < 2; mt++)
#pragma unroll
        for (int nt = 0; nt < 4; nt++) wmma::fill_fragment(acc[mt][nt], 0.f);

#pragma unroll
    for (int ks = 0; ks < 8; ks++) {
        int k = ks * 16;
        wmma::fragment<wmma::matrix_a, 16, 16, 16, __half, wmma::row_major> af[2];
        wmma::fragment<wmma::matrix_b, 16, 16, 16, __half, wmma::row_major> bf[4];
#pragma unroll
        for (int mt = 0; mt < 2; mt++)
            wmma::load_matrix_sync(af[mt], &As[(wm * 32 + mt * 16) * LDA2 + k], LDA2);
#pragma unroll
        for (int nt = 0; nt < 4; nt++)
            wmma::load_matrix_sync(bf[nt], &Bs[k * LDB2 + wn * 64 + nt * 16], LDB2);
#pragma unroll
        for (int mt = 0; mt < 2; mt++)
#pragma unroll
            for (int nt = 0; nt < 4; nt++)
                wmma::mma_sync(acc[mt][nt], af[mt], bf[nt], acc[mt][nt]);
    }
    __syncthreads();

#pragma unroll
    for (int mt = 0; mt < 2; mt++)
#pragma unroll
        for (int nt = 0; nt < 4; nt++)
            wmma::store_matrix_sync(&Ts[(wm * 32 + mt * 16) * LDT + wn * 64 + nt * 16],
                                    acc[mt][nt], LDT, wmma::mem_row_major);
    __syncthreads();

    int r0 = wid * 8;
#pragma unroll
    for (int rr = 0; rr < 8; rr++) {
        int r = r0 + rr;
        int gr = rowBase + r;
        float tv[8];
#pragma unroll
        for (int j = 0; j < 8; j++) {
            int cc = lane + 32 * j;
            tv[j] = fmaxf(Ts[r * LDT + cc] + sb1[cc], 0.f);
        }
        float o[A_DIM];
#pragma unroll
        for (int a = 0; a < A_DIM; a++) {
            float p = 0.f;
#pragma unroll
            for (int j = 0; j < 8; j++)
                p = fmaf(tv[j], sW2[(lane + 32 * j) * A_DIM + a], p);
#pragma unroll
            for (int off = 16; off; off >>= 1) p += __shfl_xor_sync(0xffffffffu, p, off);
            o[a] = p;
        }
        if (lane == 0 && gr < N_NODES) {
#pragma unroll
            for (int a = 0; a < A_DIM; a++)
                out[(size_t)gr * A_DIM + a] = o[a] + sb2[a];
        }
    }
}

// ---------------- launcher ----------------
extern "C" void kernel_launch(void* const* d_in, const int* in_sizes, int n_in,
                              void* d_out, int out_size) {
    const float* x     = (const float*)d_in[0];
    const void*  ei    = d_in[1];
    const float* W_enc = (const float*)d_in[2];
    const float* b_enc = (const float*)d_in[3];
    const float* W_gcn = (const float*)d_in[4];
    const float* b_gcn = (const float*)d_in[5];
    const float* W1    = (const float*)d_in[6];
    const float* b1    = (const float*)d_in[7];
    const float* W2    = (const float*)d_in[8];
    const float* b2    = (const float*)d_in[9];
    float* out = (float*)d_out;

    static cudaStream_t s2 = nullptr;
    static cudaEvent_t evF = nullptr, evFill = nullptr;
    if (!s2) {
        cudaStreamCreateWithFlags(&s2, cudaStreamNonBlocking);
        cudaEventCreateWithFlags(&evF,    cudaEventDisableTiming);
        cudaEventCreateWithFlags(&evFill, cudaEventDisableTiming);
        cudaFuncSetAttribute(k_enc,   cudaFuncAttributeMaxDynamicSharedMemorySize, 139264);
        cudaFuncSetAttribute(k_w1out, cudaFuncAttributeMaxDynamicSharedMemorySize, 135168);
    }

    // fork: CSR build on s2 (4 kernels)
    cudaEventRecord(evF, 0);
    cudaStreamWaitEvent(s2, evF, 0);
    k_init<<<cdiv(N_NODES, 256), 256, 0, s2>>>(ei);
    k_hist<<<cdiv(N_EDGES / 8, 256), 256, 0, s2>>>(ei);
    k_scan<<<NBLK_SCAN, 1024, 0, s2>>>();
    k_fill<<<cdiv(N_EDGES / 8, 256), 256, 0, s2>>>(ei);
    cudaEventRecord(evFill, s2);

    // main: merged converts + encoder (overlap CSR build)
    k_cvtAll<<<cdiv(XN4 + 16384, 256), 256>>>(x, W1, W_gcn, W_enc);
    k_enc<<<N_PAD / 128, 256, 139264>>>(b_enc);

    // join: aggregation then MLP head
    cudaStreamWaitEvent(0, evFill, 0);
    k_agg<<<cdiv(N_NODES / 2 * 32, 256), 256>>>(b_gcn);
    k_w1out<<<N_PAD / 128, 512, 135168>>>(b1, W2, b2, out);
}

// round 17
// speedup vs baseline: 1.0123x; 1.0123x over previous
#include <cuda_runtime.h>
#include <cuda_fp16.h>
#include <mma.h>
#include <cstdint>

using namespace nvcuda;

#define N_NODES 100000
#define N_PAD   100096   // 782 * 128
#define N_EDGES 3200000
#define H 128
#define HQ 256
#define A_DIM 10
#define NBLK_SCAN 98
#define XN4 (N_NODES * H / 4)   // 3,200,000 float4 slots for x

static inline int cdiv(int a, int b) { return (a + b - 1) / b; }

// ---------------- scratch ----------------
__device__ __half g_x16[(size_t)N_PAD * H];   // fp16 copy of x
__device__ __half g_xw16[(size_t)N_PAD * H];  // fp16 relu(x@We+be)@Wg (UNscaled)
__device__ __half g_h216[(size_t)N_PAD * H];  // fp16 relu(gcn agg)
__device__ __half g_W116[HQ * H];             // fp16 W1 [128,256]
__device__ __half g_Wg16[H * H];              // fp16 W_gcn
__device__ __half g_We16[H * H];              // fp16 W_enc
__device__ float  g_dinv[N_NODES];
__device__ int    g_deg[N_NODES];
__device__ int    g_rowptr[N_NODES + 1];
__device__ int    g_csrc[N_EDGES];
__device__ unsigned g_dr[N_EDGES];            // packed: dst | (rank << 17)
__device__ int    g_is32;
__device__ unsigned long long g_desc[NBLK_SCAN];   // decoupled-lookback descriptors

// ---------------- cp.async helpers ----------------
__device__ __forceinline__ void cp16(void* s, const void* g, bool p) {
    uint32_t sa = (uint32_t)__cvta_generic_to_shared(s);
    int sz = p ? 16 : 0;
    asm volatile("cp.async.cg.shared.global [%0], [%1], 16, %2;\n"
                 :: "r"(sa), "l"(g), "r"(sz));
}
__device__ __forceinline__ void cp_commit() {
    asm volatile("cp.async.commit_group;\n");
}
template <int NN>
__device__ __forceinline__ void cp_wait() {
    asm volatile("cp.async.wait_group %0;\n" :: "n"(NN));
}

// ---------------- merged fp32 -> fp16 conversion (x + all weights) ----------------
__global__ void k_cvtAll(const float* __restrict__ x,  const float* __restrict__ W1,
                         const float* __restrict__ Wg, const float* __restrict__ We) {
    int i = blockIdx.x * blockDim.x + threadIdx.x;
    const float* src; __half* dst; int off;
    if (i < XN4)               { src = x;  dst = g_x16;  off = i; }
    else if (i < XN4 + 8192)   { src = W1; dst = g_W116; off = i - XN4; }
    else if (i < XN4 + 12288)  { src = Wg; dst = g_Wg16; off = i - XN4 - 8192; }
    else if (i < XN4 + 16384)  { src = We; dst = g_We16; off = i - XN4 - 12288; }
    else return;
    float4 v = *(const float4*)&src[(size_t)off * 4];
    __half2 h0 = __floats2half2_rn(v.x, v.y);
    __half2 h1 = __floats2half2_rn(v.z, v.w);
    uint2 u;
    u.x = *(uint32_t*)&h0;
    u.y = *(uint32_t*)&h1;
    *(uint2*)&dst[(size_t)off * 4] = u;
}

// ---------------- init: dtype detect + zero deg + zero scan descriptors ----------------
__global__ void k_init(const void* ei) {
    int i = blockIdx.x * blockDim.x + threadIdx.x;
    if (i < N_NODES) g_deg[i] = 0;
    if (i < NBLK_SCAN) g_desc[i] = 0ull;
    if (i == 0) {
        const long long* p = (const long long*)ei;
        int is32 = 0;
        for (int k = 0; k < 64; k++) {
            long long v = p[k];
            if (v < 0 || v >= (long long)N_NODES) { is32 = 1; break; }
        }
        g_is32 = is32;
    }
}

// histogram over dst half; 4 edges/thread; store packed dst|rank<<17
__global__ void k_hist(const void* ei) {
    int i = blockIdx.x * blockDim.x + threadIdx.x;
    int base = i * 4;
    if (base >= N_EDGES) return;
    int d0, d1, d2, d3;
    if (g_is32) {
        int4 p = ((const int4*)ei)[N_EDGES / 4 + i];
        d0 = p.x; d1 = p.y; d2 = p.z; d3 = p.w;
    } else {
        longlong2 a = ((const longlong2*)ei)[N_EDGES / 2 + i * 2];
        longlong2 b = ((const longlong2*)ei)[N_EDGES / 2 + i * 2 + 1];
        d0 = (int)a.x; d1 = (int)a.y; d2 = (int)b.x; d3 = (int)b.y;
    }
    unsigned r0 = (unsigned)atomicAdd(&g_deg[d0], 1);
    unsigned r1 = (unsigned)atomicAdd(&g_deg[d1], 1);
    unsigned r2 = (unsigned)atomicAdd(&g_deg[d2], 1);
    unsigned r3 = (unsigned)atomicAdd(&g_deg[d3], 1);
    uint4 pk;
    pk.x = (unsigned)d0 | (r0 << 17);
    pk.y = (unsigned)d1 | (r1 << 17);
    pk.z = (unsigned)d2 | (r2 << 17);
    pk.w = (unsigned)d3 | (r3 << 17);
    *(uint4*)&g_dr[base] = pk;
}

// ---------- single-kernel scan: decoupled lookback (98 co-resident blocks) ----------
__global__ __launch_bounds__(1024) void k_scan() {
    __shared__ int warpsum[32];
    __shared__ int s_prefix;
    const int b = blockIdx.x;
    int tid = threadIdx.x, lane = tid & 31, wid = tid >> 5;
    int i = b * 1024 + tid;
    int v = (i < N_NODES) ? g_deg[i] : 0;
    int x = v;
#pragma unroll
    for (int off = 1; off < 32; off <<= 1) {
        int y = __shfl_up_sync(0xffffffffu, x, off);
        if (lane >= off) x += y;
    }
    if (lane == 31) warpsum[wid] = x;
    __syncthreads();
    if (wid == 0) {
        int w = warpsum[lane];
#pragma unroll
        for (int off = 1; off < 32; off <<= 1) {
            int y = __shfl_up_sync(0xffffffffu, w, off);
            if (lane >= off) w += y;
        }
        warpsum[lane] = w;
    }
    __syncthreads();
    int incl = x + (wid > 0 ? warpsum[wid - 1] : 0);
    int blocktotal = warpsum[31];

    if (tid == 0) {
        unsigned long long pub =
            ((unsigned long long)(b == 0 ? 2 : 1) << 62) | (unsigned)blocktotal;
        atomicExch(&g_desc[b], pub);
        if (b == 0) s_prefix = 0;
    }

    if (b > 0 && wid == 0) {
        int prefix = 0;
        int j = b - 1;
        while (true) {
            int idx = j - lane;
            int st = 0; unsigned val = 0;
            if (idx >= 0) {
                unsigned long long v64;
                do {
                    v64 = atomicAdd(&g_desc[idx], 0ull);
                    st = (int)(v64 >> 62);
                } while (st == 0);
                val = (unsigned)(v64 & 0xffffffffu);
            }
            unsigned inclmask = __ballot_sync(0xffffffffu, idx >= 0 && st == 2);
            if (inclmask) {
                int closest = __ffs(inclmask) - 1;
                int contrib = (lane <= closest) ? (int)val : 0;
#pragma unroll
                for (int o = 16; o; o >>= 1) contrib += __shfl_xor_sync(0xffffffffu, contrib, o);
                prefix += contrib;
                break;
            } else {
                int contrib = (idx >= 0) ? (int)val : 0;
#pragma unroll
                for (int o = 16; o; o >>= 1) contrib += __shfl_xor_sync(0xffffffffu, contrib, o);
                prefix += contrib;
                j -= 32;
            }
        }
        if (lane == 0) {
            atomicExch(&g_desc[b], (2ull << 62) | (unsigned)(prefix + blocktotal));
            s_prefix = prefix;
        }
    }
    __syncthreads();
    int prefix = s_prefix;

    if (i < N_NODES) {
        g_rowptr[i] = prefix + (incl - v);
        g_dinv[i] = rsqrtf((float)(v + 1));
    }
    if (b == 0 && tid == 0) g_rowptr[N_NODES] = N_EDGES;
}

// fill CSR: atomic-free, pos = rowptr[dst] + rank (packed)
__global__ void k_fill(const void* ei) {
    int i = blockIdx.x * blockDim.x + threadIdx.x;
    int base = i * 4;
    if (base >= N_EDGES) return;
    int s0, s1, s2, s3;
    if (g_is32) {
        int4 sv = ((const int4*)ei)[i];
        s0 = sv.x; s1 = sv.y; s2 = sv.z; s3 = sv.w;
    } else {
        longlong2 a = ((const longlong2*)ei)[i * 2];
        longlong2 b = ((const longlong2*)ei)[i * 2 + 1];
        s0 = (int)a.x; s1 = (int)a.y; s2 = (int)b.x; s3 = (int)b.y;
    }
    uint4 pk = *(const uint4*)&g_dr[base];
    g_csrc[g_rowptr[pk.x & 0x1FFFFu] + (pk.x >> 17)] = s0;
    g_csrc[g_rowptr[pk.y & 0x1FFFFu] + (pk.y >> 17)] = s1;
    g_csrc[g_rowptr[pk.z & 0x1FFFFu] + (pk.z >> 17)] = s2;
    g_csrc[g_rowptr[pk.w & 0x1FFFFu] + (pk.w >> 17)] = s3;
}

// ========== all-fp16 fused encoder + GCN-weight GEMM, single-shot ==========
#define LDH 136       // halves
#define LDW 132       // floats

__global__ __launch_bounds__(256) void k_enc(const float* __restrict__ b_enc)
{
    extern __shared__ float pool[];
    __half* Hh  = (__half*)pool;                 // 128*136 h
    __half* Wgh = (__half*)(pool + 8704);
    __half* Ah  = (__half*)(pool + 17408);
    __half* Weh = (__half*)(pool + 26112);
    float*  Ts  = pool + 17408;                  // aliases Ah+Weh
    __shared__ float sbe[128];

    const int tid = threadIdx.x;
    const int wid = tid >> 5;
    const int wm = wid & 3, wn = wid >> 2;
    const int rowBase = blockIdx.x * 128;

    if (tid < 128) sbe[tid] = b_enc[tid];

#pragma unroll
    for (int i = 0; i < 8; i++) {
        int slot = tid + i * 256;
        int r = slot >> 4, c8 = (slot & 15) * 8;
        int gr = rowBase + r;
        cp16(&Ah[r * LDH + c8],  &g_x16[(size_t)gr * 128 + c8], gr < N_NODES);
        cp16(&Weh[r * LDH + c8], &g_We16[r * 128 + c8], true);
        cp16(&Wgh[r * LDH + c8], &g_Wg16[r * 128 + c8], true);
    }
    cp_commit();
    cp_wait<0>();
    __syncthreads();

    wmma::fragment<wmma::accumulator, 16, 16, 16, float> acc[2][4];
#pragma unroll
    for (int mt = 0; mt < 2; mt++)
#pragma unroll
        for (int nt = 0; nt < 4; nt++) wmma::fill_fragment(acc[mt][nt], 0.f);

#pragma unroll
    for (int ks = 0; ks < 8; ks++) {
        int k = ks * 16;
        wmma::fragment<wmma::matrix_a, 16, 16, 16, __half, wmma::row_major> af[2];
        wmma::fragment<wmma::matrix_b, 16, 16, 16, __half, wmma::row_major> bf[4];
#pragma unroll
        for (int mt = 0; mt < 2; mt++)
            wmma::load_matrix_sync(af[mt], &Ah[(wm * 32 + mt * 16) * LDH + k], LDH);
#pragma unroll
        for (int nt = 0; nt < 4; nt++)
            wmma::load_matrix_sync(bf[nt], &Weh[k * LDH + wn * 64 + nt * 16], LDH);
#pragma unroll
        for (int mt = 0; mt < 2; mt++)
#pragma unroll
            for (int nt = 0; nt < 4; nt++)
                wmma::mma_sync(acc[mt][nt], af[mt], bf[nt], acc[mt][nt]);
    }
    __syncthreads();

#pragma unroll
    for (int mt = 0; mt < 2; mt++)
#pragma unroll
        for (int nt = 0; nt < 4; nt++)
            wmma::store_matrix_sync(&Ts[(wm * 32 + mt * 16) * LDW + wn * 64 + nt * 16],
                                    acc[mt][nt], LDW, wmma::mem_row_major);
    __syncthreads();

#pragma unroll
    for (int i = 0; i < 16; i++) {
        int slot = tid + i * 256;
        int r = slot >> 5, c4 = (slot & 31) * 4;
        float4 v = *(float4*)&Ts[r * LDW + c4];
        __half2 h0 = __floats2half2_rn(fmaxf(v.x + sbe[c4 + 0], 0.f),
                                       fmaxf(v.y + sbe[c4 + 1], 0.f));
        __half2 h1 = __floats2half2_rn(fmaxf(v.z + sbe[c4 + 2], 0.f),
                                       fmaxf(v.w + sbe[c4 + 3], 0.f));
        uint2 u;
        u.x = *(uint32_t*)&h0;
        u.y = *(uint32_t*)&h1;
        *(uint2*)&Hh[r * LDH + c4] = u;
    }
    __syncthreads();

#pragma unroll
    for (int mt = 0; mt < 2; mt++)
#pragma unroll
        for (int nt = 0; nt < 4; nt++) wmma::fill_fragment(acc[mt][nt], 0.f);

#pragma unroll
    for (int ks = 0; ks < 8; ks++) {
        int k = ks * 16;
        wmma::fragment<wmma::matrix_a, 16, 16, 16, __half, wmma::row_major> af[2];
        wmma::fragment<wmma::matrix_b, 16, 16, 16, __half, wmma::row_major> bf[4];
#pragma unroll
        for (int mt = 0; mt < 2; mt++)
            wmma::load_matrix_sync(af[mt], &Hh[(wm * 32 + mt * 16) * LDH + k], LDH);
#pragma unroll
        for (int nt = 0; nt < 4; nt++)
            wmma::load_matrix_sync(bf[nt], &Wgh[k * LDH + wn * 64 + nt * 16], LDH);
#pragma unroll
        for (int mt = 0; mt < 2; mt++)
#pragma unroll
            for (int nt = 0; nt < 4; nt++)
                wmma::mma_sync(acc[mt][nt], af[mt], bf[nt], acc[mt][nt]);
    }
    __syncthreads();

#pragma unroll
    for (int mt = 0; mt < 2; mt++)
#pragma unroll
        for (int nt = 0; nt < 4; nt++)
            wmma::store_matrix_sync(&Ts[(wm * 32 + mt * 16) * LDW + wn * 64 + nt * 16],
                                    acc[mt][nt], LDW, wmma::mem_row_major);
    __syncthreads();

#pragma unroll
    for (int i = 0; i < 16; i++) {
        int slot = tid + i * 256;
        int r = slot >> 5, c4 = (slot & 31) * 4;
        int gr = rowBase + r;
        float4 v = *(float4*)&Ts[r * LDW + c4];
        __half2 h0 = __floats2half2_rn(v.x, v.y);
        __half2 h1 = __floats2half2_rn(v.z, v.w);
        uint2 u;
        u.x = *(uint32_t*)&h0;
        u.y = *(uint32_t*)&h1;
        *(uint2*)&g_xw16[(size_t)gr * 128 + c4] = u;
    }
}

// ------- GCN aggregation: 2 nodes/warp, 16 lanes x 16B per row -------
__device__ __forceinline__ void fma8(float* acc, float c, uint4 u) {
    __half2* h = (__half2*)&u;
#pragma unroll
    for (int q = 0; q < 4; q++) {
        float2 f = __half22float2(h[q]);
        acc[q * 2]     = fmaf(c, f.x, acc[q * 2]);
        acc[q * 2 + 1] = fmaf(c, f.y, acc[q * 2 + 1]);
    }
}

__global__ void k_agg(const float* __restrict__ b_gcn) {
    int warpId = (blockIdx.x * blockDim.x + threadIdx.x) >> 5;
    int lane = threadIdx.x & 31;
    int sub = lane >> 4;
    int l16 = lane & 15;
    unsigned hmask = sub ? 0xFFFF0000u : 0x0000FFFFu;
    int gw = warpId * 2 + sub;
    if (gw >= N_NODES) return;

    int beg = g_rowptr[gw];
    int end = g_rowptr[gw + 1];

    float acc[8];
#pragma unroll
    for (int q = 0; q < 8; q++) acc[q] = 0.f;

    const int colh = l16 * 8;

    for (int base = beg; base < end; base += 16) {
        int e = base + l16;
        int s = (e < end) ? g_csrc[e] : 0;
        int cnt = min(16, end - base);
        if (cnt == 16) {
#pragma unroll
            for (int j = 0; j < 16; j++) {
                int sj = __shfl_sync(hmask, s, sub * 16 + j);
                float c = g_dinv[sj];
                uint4 u = *(const uint4*)&g_xw16[(size_t)sj * 128 + colh];
                fma8(acc, c, u);
            }
        } else {
            for (int j = 0; j < cnt; j++) {
                int sj = __shfl_sync(hmask, s, sub * 16 + j);
                float c = g_dinv[sj];
                uint4 u = *(const uint4*)&g_xw16[(size_t)sj * 128 + colh];
                fma8(acc, c, u);
            }
        }
    }

    float di = g_dinv[gw];
    {
        uint4 u = *(const uint4*)&g_xw16[(size_t)gw * 128 + colh];
        fma8(acc, di, u);
    }

    float4 b0 = *(const float4*)&b_gcn[colh];
    float4 b1 = *(const float4*)&b_gcn[colh + 4];
    float bb[8] = {b0.x, b0.y, b0.z, b0.w, b1.x, b1.y, b1.z, b1.w};
    __half2 ho[4];
#pragma unroll
    for (int q = 0; q < 4; q++) {
        float ox = fmaxf(fmaf(di, acc[q * 2],     bb[q * 2]),     0.f);
        float oy = fmaxf(fmaf(di, acc[q * 2 + 1], bb[q * 2 + 1]), 0.f);
        ho[q] = __floats2half2_rn(ox, oy);
    }
    *(uint4*)&g_h216[(size_t)gw * 128 + colh] = *(uint4*)ho;
}

// ========== fused MLP head (fp16 wmma, single K stage) ==========
#define LDA2 136     // halves
#define LDB2 264     // halves
#define LDT 264      // floats

__global__ __launch_bounds__(512) void k_w1out(
    const float* __restrict__ b1, const float* __restrict__ W2,
    const float* __restrict__ b2, float* __restrict__ out)
{
    extern __shared__ float pool[];
    __half* As = (__half*)pool;                 // 128*136 h
    __half* Bs = (__half*)pool + 128 * LDA2;    // 128*264 h
    float*  Ts = pool;                          // alias: 128*264 f
    __shared__ float sW2[HQ * A_DIM];
    __shared__ float sb1[HQ];
    __shared__ float sb2[A_DIM];

    const int tid = threadIdx.x;
    const int wid = tid >> 5, lane = tid & 31;
    const int wm = wid & 3, wn = wid >> 2;
    const int rowBase = blockIdx.x * 128;

    for (int j = tid; j < HQ * A_DIM; j += 512) sW2[j] = W2[j];
    for (int j = tid; j < HQ; j += 512) sb1[j] = b1[j];
    if (tid < A_DIM) sb2[tid] = b2[tid];

#pragma unroll
    for (int i = 0; i < 4; i++) {
        int slot = tid + i * 512;
        int r = slot >> 4, c8 = (slot & 15) * 8;
        cp16(&As[r * LDA2 + c8], &g_h216[(size_t)(rowBase + r) * 128 + c8], true);
    }
#pragma unroll
    for (int i = 0; i < 8; i++) {
        int slot = tid + i * 512;
        int r = slot >> 5, c8 = (slot & 31) * 8;
        cp16(&Bs[r * LDB2 + c8], &g_W116[(size_t)r * 256 + c8], true);
    }
    cp_commit();
    cp_wait<0>();
    __syncthreads();

    wmma::fragment<wmma::accumulator, 16, 16, 16, float> acc[2][4];
#pragma unroll
    for (int mt = 0; mt < 2; mt++)
#pragma unroll
        for (int nt = 0; nt < 4; nt++) wmma::fill_fragment(acc[mt][nt], 0.f);

#pragma unroll
    for (int ks = 0; ks < 8; ks++) {
        int k = ks * 16;
        wmma::fragment<wmma::matrix_a, 16, 16, 16, __half, wmma::row_major> af[2];
        wmma::fragment<wmma::matrix_b, 16, 16, 16, __half, wmma::row_major> bf[4];
#pragma unroll
        for (int mt = 0; mt < 2; mt++)
            wmma::load_matrix_sync(af[mt], &As[(wm * 32 + mt * 16) * LDA2 + k], LDA2);
#pragma unroll
        for (int nt = 0; nt < 4; nt++)
            wmma::load_matrix_sync(bf[nt], &Bs[k * LDB2 + wn * 64 + nt * 16], LDB2);
#pragma unroll
        for (int mt = 0; mt < 2; mt++)
#pragma unroll
            for (int nt = 0; nt < 4; nt++)
                wmma::mma_sync(acc[mt][nt], af[mt], bf[nt], acc[mt][nt]);
    }
    __syncthreads();

#pragma unroll
    for (int mt = 0; mt < 2; mt++)
#pragma unroll
        for (int nt = 0; nt < 4; nt++)
            wmma::store_matrix_sync(&Ts[(wm * 32 + mt * 16) * LDT + wn * 64 + nt * 16],
                                    acc[mt][nt], LDT, wmma::mem_row_major);
    __syncthreads();

    int r0 = wid * 8;
#pragma unroll
    for (int rr = 0; rr < 8; rr++) {
        int r = r0 + rr;
        int gr = rowBase + r;
        float tv[8];
#pragma unroll
        for (int j = 0; j < 8; j++) {
            int cc = lane + 32 * j;
            tv[j] = fmaxf(Ts[r * LDT + cc] + sb1[cc], 0.f);
        }
        float o[A_DIM];
#pragma unroll
        for (int a = 0; a < A_DIM; a++) {
            float p = 0.f;
#pragma unroll
            for (int j = 0; j < 8; j++)
                p = fmaf(tv[j], sW2[(lane + 32 * j) * A_DIM + a], p);
#pragma unroll
            for (int off = 16; off; off >>= 1) p += __shfl_xor_sync(0xffffffffu, p, off);
            o[a] = p;
        }
        if (lane == 0 && gr < N_NODES) {
#pragma unroll
            for (int a = 0; a < A_DIM; a++)
                out[(size_t)gr * A_DIM + a] = o[a] + sb2[a];
        }
    }
}

// ---------------- launcher ----------------
extern "C" void kernel_launch(void* const* d_in, const int* in_sizes, int n_in,
                              void* d_out, int out_size) {
    const float* x     = (const float*)d_in[0];
    const void*  ei    = d_in[1];
    const float* W_enc = (const float*)d_in[2];
    const float* b_enc = (const float*)d_in[3];
    const float* W_gcn = (const float*)d_in[4];
    const float* b_gcn = (const float*)d_in[5];
    const float* W1    = (const float*)d_in[6];
    const float* b1    = (const float*)d_in[7];
    const float* W2    = (const float*)d_in[8];
    const float* b2    = (const float*)d_in[9];
    float* out = (float*)d_out;

    static cudaStream_t s2 = nullptr;
    static cudaEvent_t evF = nullptr, evFill = nullptr;
    if (!s2) {
        cudaStreamCreateWithFlags(&s2, cudaStreamNonBlocking);
        cudaEventCreateWithFlags(&evF,    cudaEventDisableTiming);
        cudaEventCreateWithFlags(&evFill, cudaEventDisableTiming);
        cudaFuncSetAttribute(k_enc,   cudaFuncAttributeMaxDynamicSharedMemorySize, 139264);
        cudaFuncSetAttribute(k_w1out, cudaFuncAttributeMaxDynamicSharedMemorySize, 135168);
    }

    // fork: CSR build on s2 (4 kernels)
    cudaEventRecord(evF, 0);
    cudaStreamWaitEvent(s2, evF, 0);
    k_init<<<cdiv(N_NODES, 256), 256, 0, s2>>>(ei);
    k_hist<<<cdiv(N_EDGES / 4, 256), 256, 0, s2>>>(ei);
    k_scan<<<NBLK_SCAN, 1024, 0, s2>>>();
    k_fill<<<cdiv(N_EDGES / 4, 256), 256, 0, s2>>>(ei);
    cudaEventRecord(evFill, s2);

    // main: merged converts + encoder (overlap CSR build)
    k_cvtAll<<<cdiv(XN4 + 16384, 256), 256>>>(x, W1, W_gcn, W_enc);
    k_enc<<<N_PAD / 128, 256, 139264>>>(b_enc);

    // join: aggregation then MLP head
    cudaStreamWaitEvent(0, evFill, 0);
    k_agg<<<cdiv(N_NODES / 2 * 32, 256), 256>>>(b_gcn);
    k_w1out<<<N_PAD / 128, 512, 135168>>>(b1, W2, b2, out);
}